// round 16
// baseline (speedup 1.0000x reference)
#include <cuda_runtime.h>
#include <cuda_bf16.h>
#include <cuda_fp16.h>
#include <math.h>
#include <stdint.h>

#define BATCH   8
#define SEQ     2048
#define EMBED   1024
#define QKVD    3072

// ---------------- scratch (device globals; no allocs allowed) ---------------
__device__ __half g_Vh    [(size_t)BATCH * SEQ * EMBED];   // fp16 V (row-major)
__device__ float  g_scores[(size_t)BATCH * SEQ * SEQ];
__device__ __half g_A1[(size_t)BATCH * SEQ * EMBED];       // x fp16
__device__ __half g_B1[(size_t)QKVD * EMBED];              // W fp16
__device__ __half g_QA[(size_t)BATCH * SEQ * EMBED];       // Q fp16
__device__ __half g_KB[(size_t)BATCH * SEQ * EMBED];       // K fp16
__device__ __half g_VB[(size_t)BATCH * EMBED * SEQ];       // V^T fp16
__device__ __half g_PA[(size_t)BATCH * SEQ * SEQ];         // probs fp16

// ---------------- asm helpers ------------------------------------------------
__device__ __forceinline__ uint32_t smem_u32(const void* p) {
    uint32_t a;
    asm("{ .reg .u64 t; cvta.to.shared.u64 t, %1; cvt.u32.u64 %0, t; }" : "=r"(a) : "l"(p));
    return a;
}
#define CP_ASYNC16(dst, src) \
    asm volatile("cp.async.cg.shared.global [%0], [%1], 16;" :: "r"(dst), "l"(src))
#define CP_COMMIT() asm volatile("cp.async.commit_group;" ::: "memory")
#define CP_WAIT1()  asm volatile("cp.async.wait_group 1;"  ::: "memory")
#define LDMX4(r, addr) \
    asm volatile("ldmatrix.sync.aligned.m8n8.x4.shared.b16 {%0,%1,%2,%3}, [%4];" \
        : "=r"((r)[0]), "=r"((r)[1]), "=r"((r)[2]), "=r"((r)[3]) : "r"(addr))
#define MMA16816_F16(d, a, b) \
    asm volatile("mma.sync.aligned.m16n8k16.row.col.f32.f16.f16.f32 " \
        "{%0,%1,%2,%3}, {%4,%5,%6,%7}, {%8,%9}, {%0,%1,%2,%3};" \
        : "+f"((d)[0]), "+f"((d)[1]), "+f"((d)[2]), "+f"((d)[3]) \
        : "r"((a)[0]), "r"((a)[1]), "r"((a)[2]), "r"((a)[3]), "r"((b)[0]), "r"((b)[1]))
// fp16-accumulator variant: D,C packed as 2 x b32 (4 halves)
#define MMA16816_HACC(d, a, b) \
    asm volatile("mma.sync.aligned.m16n8k16.row.col.f16.f16.f16.f16 " \
        "{%0,%1}, {%2,%3,%4,%5}, {%6,%7}, {%0,%1};" \
        : "+r"((d)[0]), "+r"((d)[1]) \
        : "r"((a)[0]), "r"((a)[1]), "r"((a)[2]), "r"((a)[3]), "r"((b)[0]), "r"((b)[1]))

// ---------------- tensor-core GEMM -------------------------------------------
// C[m,n] = alpha * sum_k A[m,k] B[n,k]   (A, B row-major fp16, K-major)
// CTA tile 128x128, K-chunk 64, 3-stage cp.async, single-sync multistage loop.
// 256 threads = 8 warps (2m x 4n), warp tile 64x32, mma.m16n8k16.
// HACC=false: fp32-acc MMAs, register double-buffered fragments (GEMM1 path)
// HACC=true : fp16-acc MMA pairs (K=32 spans) flushed into fp32 accumulators
// MODE 0: plain epilogue (alpha scale) -> fp32 C
// MODE 1: fused qkv epilogue (bias + single-fp16 writes to QA/KB/Vh)
#define LDT     72                       // smem row pitch in halves (144 B)
#define ATILE_H (128 * LDT)
#define STAGE_H (2 * ATILE_H)            // A+B tile per stage (halves)
#define NSTAGE  3
#define SMEM_B  (NSTAGE * STAGE_H * 2)   // 110592 bytes

__device__ __forceinline__ void load_chunk(uint32_t sb, int stage,
    const __half* __restrict__ Ag, const __half* __restrict__ Bg,
    int K, int k0, int tid)
{
    const int r = tid >> 1;
    const int c = (tid & 1) * 32;
    const uint32_t base = sb + (uint32_t)stage * (STAGE_H * 2) + (r * LDT + c) * 2;
    const __half* as = Ag + (size_t)r * K + k0 + c;
    const __half* bs = Bg + (size_t)r * K + k0 + c;
    #pragma unroll
    for (int i = 0; i < 4; ++i) CP_ASYNC16(base + i * 16, as + i * 8);
    #pragma unroll
    for (int i = 0; i < 4; ++i) CP_ASYNC16(base + ATILE_H * 2 + i * 16, bs + i * 8);
}

template<int MODE, bool HACC>
__global__ void __launch_bounds__(256, 2) mma_gemm(
    const __half* __restrict__ A, const __half* __restrict__ B,
    const float* __restrict__ bias, float* __restrict__ C,
    __half* __restrict__ QA, __half* __restrict__ KB, __half* __restrict__ Vh,
    int K, int ldc, long long sA, long long sB, long long sC, float alpha)
{
    extern __shared__ char smem[];
    const uint32_t sb = smem_u32(smem);
    const int tid = threadIdx.x;
    const int lane = tid & 31;
    const int wid = tid >> 5;
    const int wm = (wid & 1) * 64;
    const int wn = (wid >> 1) * 32;

    const __half* Ag = A + blockIdx.z * sA + (size_t)(blockIdx.y * 128) * K;
    const __half* Bg = B + blockIdx.z * sB + (size_t)(blockIdx.x * 128) * K;

    const int ar = (lane & 7) + ((lane >> 3) & 1) * 8;
    const int ak = (lane >> 4) * 8;
    const int bn = (lane & 7) + ((lane >> 4) & 1) * 8;
    const int bk = ((lane >> 3) & 1) * 8;

    const uint32_t a_off = ((wm + ar) * LDT + ak) * 2;
    const uint32_t b_off = ((wn + bn) * LDT + bk) * 2;

    float acc[4][4][4];
    #pragma unroll
    for (int i = 0; i < 4; ++i)
        #pragma unroll
        for (int j = 0; j < 4; ++j)
            #pragma unroll
            for (int q = 0; q < 4; ++q) acc[i][j][q] = 0.0f;

    const int nch = K / 64;
    load_chunk(sb, 0, Ag, Bg, K, 0, tid);  CP_COMMIT();
    load_chunk(sb, 1, Ag, Bg, K, 64, tid); CP_COMMIT();

    for (int ch = 0; ch < nch; ++ch) {
        const int stage = ch % NSTAGE;
        CP_WAIT1();              // chunk ch resident
        __syncthreads();         // publish cp.async writes; free stage (ch-1)%3

        const uint32_t abase = sb + (uint32_t)stage * (STAGE_H * 2) + a_off;
        const uint32_t bbase = sb + (uint32_t)stage * (STAGE_H * 2) + ATILE_H * 2 + b_off;

        if (HACC) {
            // fp16-acc pairs: 2 pairs of k16 steps per chunk
            bool issued = false;
            #pragma unroll
            for (int p = 0; p < 2; ++p) {
                uint32_t a[2][4][4];
                uint32_t b[2][2][4];
                #pragma unroll
                for (int s2 = 0; s2 < 2; ++s2) {
                    #pragma unroll
                    for (int mf = 0; mf < 4; ++mf)
                        LDMX4(a[s2][mf], abase + (mf * 16 * LDT + (2 * p + s2) * 16) * 2);
                    #pragma unroll
                    for (int n2 = 0; n2 < 2; ++n2)
                        LDMX4(b[s2][n2], bbase + (n2 * 16 * LDT + (2 * p + s2) * 16) * 2);
                }
                if (!issued) {   // issue next-chunk loads after first LDSMs in flight
                    if (ch + 2 < nch) load_chunk(sb, (ch + 2) % NSTAGE, Ag, Bg, K, (ch + 2) * 64, tid);
                    CP_COMMIT();
                    issued = true;
                }
                #pragma unroll
                for (int mf = 0; mf < 4; ++mf)
                    #pragma unroll
                    for (int nf = 0; nf < 4; ++nf) {
                        uint32_t h[2] = { 0u, 0u };
                        MMA16816_HACC(h, a[0][mf], &b[0][nf >> 1][(nf & 1) * 2]);
                        MMA16816_HACC(h, a[1][mf], &b[1][nf >> 1][(nf & 1) * 2]);
                        const float2 f0 = __half22float2(*reinterpret_cast<__half2*>(&h[0]));
                        const float2 f1 = __half22float2(*reinterpret_cast<__half2*>(&h[1]));
                        acc[mf][nf][0] += f0.x;
                        acc[mf][nf][1] += f0.y;
                        acc[mf][nf][2] += f1.x;
                        acc[mf][nf][3] += f1.y;
                    }
            }
        } else {
            // fp32-acc path with register double-buffered fragments
            uint32_t afr[2][4][4];
            uint32_t bfr[2][2][4];
            #pragma unroll
            for (int mf = 0; mf < 4; ++mf)
                LDMX4(afr[0][mf], abase + (mf * 16 * LDT) * 2);
            #pragma unroll
            for (int n2 = 0; n2 < 2; ++n2)
                LDMX4(bfr[0][n2], bbase + (n2 * 16 * LDT) * 2);

            if (ch + 2 < nch) load_chunk(sb, (ch + 2) % NSTAGE, Ag, Bg, K, (ch + 2) * 64, tid);
            CP_COMMIT();

            #pragma unroll
            for (int s = 0; s < 4; ++s) {
                const int cur = s & 1;
                const int nxt = cur ^ 1;
                if (s < 3) {
                    #pragma unroll
                    for (int mf = 0; mf < 4; ++mf)
                        LDMX4(afr[nxt][mf], abase + (mf * 16 * LDT + (s + 1) * 16) * 2);
                    #pragma unroll
                    for (int n2 = 0; n2 < 2; ++n2)
                        LDMX4(bfr[nxt][n2], bbase + (n2 * 16 * LDT + (s + 1) * 16) * 2);
                }
                #pragma unroll
                for (int mf = 0; mf < 4; ++mf)
                    #pragma unroll
                    for (int nf = 0; nf < 4; ++nf)
                        MMA16816_F16(acc[mf][nf], afr[cur][mf], &bfr[cur][nf >> 1][(nf & 1) * 2]);
            }
        }
    }

    // ---------------- epilogue ----------------
    const int g  = lane >> 2;
    const int tg = lane & 3;

    if (MODE == 0) {
        float* Cg = C + blockIdx.z * sC;
        #pragma unroll
        for (int mf = 0; mf < 4; ++mf) {
            const int row0 = blockIdx.y * 128 + wm + mf * 16 + g;
            #pragma unroll
            for (int nf = 0; nf < 4; ++nf) {
                const int col = blockIdx.x * 128 + wn + nf * 8 + tg * 2;
                float2 v0 = make_float2(acc[mf][nf][0] * alpha, acc[mf][nf][1] * alpha);
                float2 v1 = make_float2(acc[mf][nf][2] * alpha, acc[mf][nf][3] * alpha);
                *reinterpret_cast<float2*>(Cg + (size_t)row0 * ldc + col) = v0;
                *reinterpret_cast<float2*>(Cg + (size_t)(row0 + 8) * ldc + col) = v1;
            }
        }
    } else {
        const int cblk = blockIdx.x * 128;
        const int region = cblk >> 10;               // 0=Q 1=K 2=V
        __half* dst = (region == 0) ? QA : (region == 1) ? KB : Vh;
        #pragma unroll
        for (int mf = 0; mf < 4; ++mf) {
            const int row0 = blockIdx.y * 128 + wm + mf * 16 + g;
            #pragma unroll
            for (int nf = 0; nf < 4; ++nf) {
                const int gcol = cblk + wn + nf * 8 + tg * 2;
                const float2 bb = *reinterpret_cast<const float2*>(bias + gcol);
                const int lcol = gcol & 1023;
                #pragma unroll
                for (int h = 0; h < 2; ++h) {
                    const int r = row0 + h * 8;
                    const __half2 hp(__float2half(acc[mf][nf][h * 2 + 0] + bb.x),
                                     __float2half(acc[mf][nf][h * 2 + 1] + bb.y));
                    *reinterpret_cast<__half2*>(dst + (size_t)r * EMBED + lcol) = hp;
                }
            }
        }
    }
}

// ---------------- fp32 -> fp16 convert (x and W in one launch) ----------------
__global__ void cvt2_kernel(const float* __restrict__ srcA, __half* __restrict__ dstA,
                            long long nA,
                            const float* __restrict__ srcB, __half* __restrict__ dstB,
                            long long nB)
{
    long long i = blockIdx.x * (long long)blockDim.x + threadIdx.x;
    const float* src;  __half* dst;  long long idx;
    if (i < nA)           { src = srcA; dst = dstA; idx = i; }
    else if (i < nA + nB) { src = srcB; dst = dstB; idx = i - nA; }
    else return;
    const float4 v = *reinterpret_cast<const float4*>(src + idx * 4);
    __half2 h0(__float2half(v.x), __float2half(v.y));
    __half2 h1(__float2half(v.z), __float2half(v.w));
    reinterpret_cast<__half2*>(dst + idx * 4)[0] = h0;
    reinterpret_cast<__half2*>(dst + idx * 4)[1] = h1;
}

// ---------------- V transpose fp16 -> fp16 (B-order, single) -----------------
__global__ void vtrans_kernel(const __half* __restrict__ Vh, __half* __restrict__ VB)
{
    __shared__ __half t[32][34];
    const int b = blockIdx.z;
    const int n0 = blockIdx.x * 32, e0 = blockIdx.y * 32;
    const int tx = threadIdx.x, ty = threadIdx.y;
    const __half* src = Vh + (size_t)b * SEQ * EMBED;
    #pragma unroll
    for (int i = 0; i < 4; ++i)
        t[ty + 8 * i][tx] = src[(size_t)(n0 + ty + 8 * i) * EMBED + e0 + tx];
    __syncthreads();
    __half* dst = VB + (size_t)b * EMBED * SEQ;
    #pragma unroll
    for (int i = 0; i < 4; ++i)
        dst[(size_t)(e0 + ty + 8 * i) * SEQ + n0 + tx] = t[tx][ty + 8 * i];
}

// ---------------- softmax -> fp16 probs --------------------------------------
__global__ void softmax_pa_kernel(const float* __restrict__ s, __half* __restrict__ PA)
{
    __shared__ float row[SEQ];
    __shared__ float red[8];
    const int tid = threadIdx.x;
    const float4* p4 = reinterpret_cast<const float4*>(s + (size_t)blockIdx.x * SEQ);
    float4* r4 = reinterpret_cast<float4*>(row);

    float lmax = -3.4e38f;
    #pragma unroll
    for (int it = 0; it < 2; ++it) {
        const float4 t = p4[tid + it * 256];
        r4[tid + it * 256] = t;
        lmax = fmaxf(lmax, fmaxf(fmaxf(t.x, t.y), fmaxf(t.z, t.w)));
    }
    #pragma unroll
    for (int o = 16; o; o >>= 1) lmax = fmaxf(lmax, __shfl_xor_sync(0xffffffffu, lmax, o));
    if ((tid & 31) == 0) red[tid >> 5] = lmax;
    __syncthreads();
    const float rmax = fmaxf(fmaxf(fmaxf(red[0], red[1]), fmaxf(red[2], red[3])),
                             fmaxf(fmaxf(red[4], red[5]), fmaxf(red[6], red[7])));
    __syncthreads();

    float lsum = 0.0f;
    #pragma unroll
    for (int it = 0; it < 2; ++it) {
        float4 t = r4[tid + it * 256];
        t.x = expf(t.x - rmax); t.y = expf(t.y - rmax);
        t.z = expf(t.z - rmax); t.w = expf(t.w - rmax);
        r4[tid + it * 256] = t;
        lsum += (t.x + t.y) + (t.z + t.w);
    }
    #pragma unroll
    for (int o = 16; o; o >>= 1) lsum += __shfl_xor_sync(0xffffffffu, lsum, o);
    if ((tid & 31) == 0) red[tid >> 5] = lsum;
    __syncthreads();
    const float inv = 1.0f / (((red[0] + red[1]) + (red[2] + red[3])) +
                              ((red[4] + red[5]) + (red[6] + red[7])));

    __half* pa = PA + (size_t)blockIdx.x * SEQ;
    #pragma unroll
    for (int it = 0; it < 2; ++it) {
        float4 t = r4[tid + it * 256];
        const int idx = (tid + it * 256) * 4;
        __half2 hp0(__float2half(t.x * inv), __float2half(t.y * inv));
        __half2 hp1(__float2half(t.z * inv), __float2half(t.w * inv));
        reinterpret_cast<__half2*>(pa + idx)[0] = hp0;
        reinterpret_cast<__half2*>(pa + idx)[1] = hp1;
    }
}

// -----------------------------------------------------------------------------
extern "C" void kernel_launch(void* const* d_in, const int* in_sizes, int n_in,
                              void* d_out, int out_size)
{
    const float* x = (const float*)d_in[0];
    const float* W = (const float*)d_in[1];
    const float* b = (const float*)d_in[2];
    float* out = (float*)d_out;

    float *sc;
    __half *Vh, *A1, *B1, *QA, *KB, *VB, *PA;
    { void* p; cudaGetSymbolAddress(&p, g_Vh);     Vh = (__half*)p; }
    { void* p; cudaGetSymbolAddress(&p, g_scores); sc = (float*)p; }
    { void* p; cudaGetSymbolAddress(&p, g_A1); A1 = (__half*)p; }
    { void* p; cudaGetSymbolAddress(&p, g_B1); B1 = (__half*)p; }
    { void* p; cudaGetSymbolAddress(&p, g_QA); QA = (__half*)p; }
    { void* p; cudaGetSymbolAddress(&p, g_KB); KB = (__half*)p; }
    { void* p; cudaGetSymbolAddress(&p, g_VB); VB = (__half*)p; }
    { void* p; cudaGetSymbolAddress(&p, g_PA); PA = (__half*)p; }

    cudaFuncSetAttribute((const void*)mma_gemm<1,false>, cudaFuncAttributeMaxDynamicSharedMemorySize, SMEM_B);
    cudaFuncSetAttribute((const void*)mma_gemm<0,true>,  cudaFuncAttributeMaxDynamicSharedMemorySize, SMEM_B);

    const long long MN = (long long)BATCH * SEQ;   // 16384

    // input converts: x -> A1 fp16, W -> B1 fp16 (single launch)
    {
        const long long nA = MN * EMBED / 4;
        const long long nB = (long long)QKVD * EMBED / 4;
        cvt2_kernel<<<(unsigned)((nA + nB + 255) / 256), 256>>>(x, A1, nA, W, B1, nB);
    }

    // GEMM1 (fused): qkv = x @ W^T + b  (Keff=1024, fp32-acc)
    //   -> QA fp16, KB fp16, Vh fp16
    mma_gemm<1,false><<<dim3(QKVD / 128, (unsigned)(MN / 128), 1), 256, SMEM_B>>>(
        A1, B1, b, nullptr, QA, KB, Vh,
        EMBED, 0, 0, 0, 0, 1.0f);

    // V transpose -> fp16
    vtrans_kernel<<<dim3(SEQ / 32, EMBED / 32, BATCH), dim3(32, 8)>>>(Vh, VB);

    // GEMM2: scores = Q @ K^T / 32   (per batch M=N=2048, Keff=1024, fp16-pair acc)
    mma_gemm<0,true><<<dim3(SEQ / 128, SEQ / 128, BATCH), 256, SMEM_B>>>(
        QA, KB, nullptr, sc, nullptr, nullptr, nullptr,
        EMBED, SEQ,
        (long long)SEQ * EMBED, (long long)SEQ * EMBED, (long long)SEQ * SEQ,
        0.03125f);

    // softmax -> fp16 probs
    softmax_pa_kernel<<<BATCH * SEQ, 256>>>(sc, PA);

    // GEMM3: out = P @ V   (per batch M=2048, N=1024, Keff=2048, fp16-pair acc)
    mma_gemm<0,true><<<dim3(EMBED / 128, SEQ / 128, BATCH), 256, SMEM_B>>>(
        PA, VB, nullptr, out, nullptr, nullptr, nullptr,
        SEQ, EMBED,
        (long long)SEQ * SEQ, (long long)EMBED * SEQ, (long long)SEQ * EMBED,
        1.0f);
}

// round 17
// speedup vs baseline: 1.1285x; 1.1285x over previous
#include <cuda_runtime.h>
#include <cuda_bf16.h>
#include <cuda_fp16.h>
#include <math.h>
#include <stdint.h>

#define BATCH   8
#define SEQ     2048
#define EMBED   1024
#define QKVD    3072

// ---------------- scratch (device globals; no allocs allowed) ---------------
__device__ __half g_Vh[(size_t)BATCH * SEQ * EMBED];   // fp16 V (row-major)
__device__ __half g_sc[(size_t)BATCH * SEQ * SEQ];     // fp16 scores
__device__ __half g_A1[(size_t)BATCH * SEQ * EMBED];   // x fp16
__device__ __half g_B1[(size_t)QKVD * EMBED];          // W fp16
__device__ __half g_QA[(size_t)BATCH * SEQ * EMBED];   // Q fp16
__device__ __half g_KB[(size_t)BATCH * SEQ * EMBED];   // K fp16
__device__ __half g_VB[(size_t)BATCH * EMBED * SEQ];   // V^T fp16
__device__ __half g_PA[(size_t)BATCH * SEQ * SEQ];     // probs fp16

// ---------------- asm helpers ------------------------------------------------
__device__ __forceinline__ uint32_t smem_u32(const void* p) {
    uint32_t a;
    asm("{ .reg .u64 t; cvta.to.shared.u64 t, %1; cvt.u32.u64 %0, t; }" : "=r"(a) : "l"(p));
    return a;
}
#define CP_ASYNC16(dst, src) \
    asm volatile("cp.async.cg.shared.global [%0], [%1], 16;" :: "r"(dst), "l"(src))
#define CP_COMMIT() asm volatile("cp.async.commit_group;" ::: "memory")
#define CP_WAIT1()  asm volatile("cp.async.wait_group 1;"  ::: "memory")
#define LDMX4(r, addr) \
    asm volatile("ldmatrix.sync.aligned.m8n8.x4.shared.b16 {%0,%1,%2,%3}, [%4];" \
        : "=r"((r)[0]), "=r"((r)[1]), "=r"((r)[2]), "=r"((r)[3]) : "r"(addr))
#define MMA16816_F16(d, a, b) \
    asm volatile("mma.sync.aligned.m16n8k16.row.col.f32.f16.f16.f32 " \
        "{%0,%1,%2,%3}, {%4,%5,%6,%7}, {%8,%9}, {%0,%1,%2,%3};" \
        : "+f"((d)[0]), "+f"((d)[1]), "+f"((d)[2]), "+f"((d)[3]) \
        : "r"((a)[0]), "r"((a)[1]), "r"((a)[2]), "r"((a)[3]), "r"((b)[0]), "r"((b)[1]))

// ---------------- tensor-core GEMM -------------------------------------------
// C[m,n] = alpha * sum_k A[m,k] B[n,k]   (A, B row-major fp16, K-major)
// CTA tile 128x128, K-chunk 64, 3-stage cp.async, single-sync multistage loop,
// register double-buffered fragments. 256 threads = 8 warps (2m x 4n),
// warp tile 64x32, mma.m16n8k16 fp16 -> fp32 acc.
// MODE 0: fp32 C epilogue (alpha)
// MODE 1: fused qkv epilogue (bias + single-fp16 writes to QA/KB/Vh)
// MODE 2: fp16 C epilogue (alpha) -> CH
#define LDT     72                       // smem row pitch in halves (144 B)
#define ATILE_H (128 * LDT)
#define STAGE_H (2 * ATILE_H)            // A+B tile per stage (halves)
#define NSTAGE  3
#define SMEM_B  (NSTAGE * STAGE_H * 2)   // 110592 bytes

__device__ __forceinline__ void load_chunk(uint32_t sb, int stage,
    const __half* __restrict__ Ag, const __half* __restrict__ Bg,
    int K, int k0, int tid)
{
    const int r = tid >> 1;
    const int c = (tid & 1) * 32;
    const uint32_t base = sb + (uint32_t)stage * (STAGE_H * 2) + (r * LDT + c) * 2;
    const __half* as = Ag + (size_t)r * K + k0 + c;
    const __half* bs = Bg + (size_t)r * K + k0 + c;
    #pragma unroll
    for (int i = 0; i < 4; ++i) CP_ASYNC16(base + i * 16, as + i * 8);
    #pragma unroll
    for (int i = 0; i < 4; ++i) CP_ASYNC16(base + ATILE_H * 2 + i * 16, bs + i * 8);
}

template<int MODE>
__global__ void __launch_bounds__(256, 2) mma_gemm(
    const __half* __restrict__ A, const __half* __restrict__ B,
    const float* __restrict__ bias, float* __restrict__ C,
    __half* __restrict__ QA, __half* __restrict__ KB, __half* __restrict__ Vh,
    int K, int ldc, long long sA, long long sB, long long sC, float alpha)
{
    extern __shared__ char smem[];
    const uint32_t sb = smem_u32(smem);
    const int tid = threadIdx.x;
    const int lane = tid & 31;
    const int wid = tid >> 5;
    const int wm = (wid & 1) * 64;
    const int wn = (wid >> 1) * 32;

    const __half* Ag = A + blockIdx.z * sA + (size_t)(blockIdx.y * 128) * K;
    const __half* Bg = B + blockIdx.z * sB + (size_t)(blockIdx.x * 128) * K;

    const int ar = (lane & 7) + ((lane >> 3) & 1) * 8;
    const int ak = (lane >> 4) * 8;
    const int bn = (lane & 7) + ((lane >> 4) & 1) * 8;
    const int bk = ((lane >> 3) & 1) * 8;

    const uint32_t a_off = ((wm + ar) * LDT + ak) * 2;
    const uint32_t b_off = ((wn + bn) * LDT + bk) * 2;

    float acc[4][4][4];
    #pragma unroll
    for (int i = 0; i < 4; ++i)
        #pragma unroll
        for (int j = 0; j < 4; ++j)
            #pragma unroll
            for (int q = 0; q < 4; ++q) acc[i][j][q] = 0.0f;

    const int nch = K / 64;
    load_chunk(sb, 0, Ag, Bg, K, 0, tid);  CP_COMMIT();
    load_chunk(sb, 1, Ag, Bg, K, 64, tid); CP_COMMIT();

    for (int ch = 0; ch < nch; ++ch) {
        const int stage = ch % NSTAGE;
        CP_WAIT1();              // chunk ch resident
        __syncthreads();         // publish cp.async writes; free stage (ch-1)%3

        const uint32_t abase = sb + (uint32_t)stage * (STAGE_H * 2) + a_off;
        const uint32_t bbase = sb + (uint32_t)stage * (STAGE_H * 2) + ATILE_H * 2 + b_off;

        // fragment ping-pong buffers
        uint32_t afr[2][4][4];
        uint32_t bfr[2][2][4];

        // prologue: load step-0 fragments first (critical path)
        #pragma unroll
        for (int mf = 0; mf < 4; ++mf)
            LDMX4(afr[0][mf], abase + (mf * 16 * LDT) * 2);
        #pragma unroll
        for (int n2 = 0; n2 < 2; ++n2)
            LDMX4(bfr[0][n2], bbase + (n2 * 16 * LDT) * 2);

        // issue next-chunk global loads AFTER the first LDSMs are in flight
        if (ch + 2 < nch) load_chunk(sb, (ch + 2) % NSTAGE, Ag, Bg, K, (ch + 2) * 64, tid);
        CP_COMMIT();

        #pragma unroll
        for (int s = 0; s < 4; ++s) {
            const int cur = s & 1;
            const int nxt = cur ^ 1;
            if (s < 3) {   // prefetch step s+1 fragments while computing step s
                #pragma unroll
                for (int mf = 0; mf < 4; ++mf)
                    LDMX4(afr[nxt][mf], abase + (mf * 16 * LDT + (s + 1) * 16) * 2);
                #pragma unroll
                for (int n2 = 0; n2 < 2; ++n2)
                    LDMX4(bfr[nxt][n2], bbase + (n2 * 16 * LDT + (s + 1) * 16) * 2);
            }
            #pragma unroll
            for (int mf = 0; mf < 4; ++mf)
                #pragma unroll
                for (int nf = 0; nf < 4; ++nf)
                    MMA16816_F16(acc[mf][nf], afr[cur][mf], &bfr[cur][nf >> 1][(nf & 1) * 2]);
        }
    }

    // ---------------- epilogue ----------------
    const int g  = lane >> 2;
    const int tg = lane & 3;

    if (MODE == 0) {
        float* Cg = C + blockIdx.z * sC;
        #pragma unroll
        for (int mf = 0; mf < 4; ++mf) {
            const int row0 = blockIdx.y * 128 + wm + mf * 16 + g;
            #pragma unroll
            for (int nf = 0; nf < 4; ++nf) {
                const int col = blockIdx.x * 128 + wn + nf * 8 + tg * 2;
                float2 v0 = make_float2(acc[mf][nf][0] * alpha, acc[mf][nf][1] * alpha);
                float2 v1 = make_float2(acc[mf][nf][2] * alpha, acc[mf][nf][3] * alpha);
                *reinterpret_cast<float2*>(Cg + (size_t)row0 * ldc + col) = v0;
                *reinterpret_cast<float2*>(Cg + (size_t)(row0 + 8) * ldc + col) = v1;
            }
        }
    } else if (MODE == 2) {
        __half* CH = reinterpret_cast<__half*>(C) + blockIdx.z * sC;
        #pragma unroll
        for (int mf = 0; mf < 4; ++mf) {
            const int row0 = blockIdx.y * 128 + wm + mf * 16 + g;
            #pragma unroll
            for (int nf = 0; nf < 4; ++nf) {
                const int col = blockIdx.x * 128 + wn + nf * 8 + tg * 2;
                __half2 h0(__float2half(acc[mf][nf][0] * alpha),
                           __float2half(acc[mf][nf][1] * alpha));
                __half2 h1(__float2half(acc[mf][nf][2] * alpha),
                           __float2half(acc[mf][nf][3] * alpha));
                *reinterpret_cast<__half2*>(CH + (size_t)row0 * ldc + col) = h0;
                *reinterpret_cast<__half2*>(CH + (size_t)(row0 + 8) * ldc + col) = h1;
            }
        }
    } else {
        const int cblk = blockIdx.x * 128;
        const int region = cblk >> 10;               // 0=Q 1=K 2=V
        __half* dst = (region == 0) ? QA : (region == 1) ? KB : Vh;
        #pragma unroll
        for (int mf = 0; mf < 4; ++mf) {
            const int row0 = blockIdx.y * 128 + wm + mf * 16 + g;
            #pragma unroll
            for (int nf = 0; nf < 4; ++nf) {
                const int gcol = cblk + wn + nf * 8 + tg * 2;
                const float2 bb = *reinterpret_cast<const float2*>(bias + gcol);
                const int lcol = gcol & 1023;
                #pragma unroll
                for (int h = 0; h < 2; ++h) {
                    const int r = row0 + h * 8;
                    const __half2 hp(__float2half(acc[mf][nf][h * 2 + 0] + bb.x),
                                     __float2half(acc[mf][nf][h * 2 + 1] + bb.y));
                    *reinterpret_cast<__half2*>(dst + (size_t)r * EMBED + lcol) = hp;
                }
            }
        }
    }
}

// ---------------- fp32 -> fp16 convert (x and W in one launch) ----------------
__global__ void cvt2_kernel(const float* __restrict__ srcA, __half* __restrict__ dstA,
                            long long nA,
                            const float* __restrict__ srcB, __half* __restrict__ dstB,
                            long long nB)
{
    long long i = blockIdx.x * (long long)blockDim.x + threadIdx.x;
    const float* src;  __half* dst;  long long idx;
    if (i < nA)           { src = srcA; dst = dstA; idx = i; }
    else if (i < nA + nB) { src = srcB; dst = dstB; idx = i - nA; }
    else return;
    const float4 v = *reinterpret_cast<const float4*>(src + idx * 4);
    __half2 h0(__float2half(v.x), __float2half(v.y));
    __half2 h1(__float2half(v.z), __float2half(v.w));
    reinterpret_cast<__half2*>(dst + idx * 4)[0] = h0;
    reinterpret_cast<__half2*>(dst + idx * 4)[1] = h1;
}

// ---------------- V transpose fp16 -> fp16 (B-order, single) -----------------
__global__ void vtrans_kernel(const __half* __restrict__ Vh, __half* __restrict__ VB)
{
    __shared__ __half t[32][34];
    const int b = blockIdx.z;
    const int n0 = blockIdx.x * 32, e0 = blockIdx.y * 32;
    const int tx = threadIdx.x, ty = threadIdx.y;
    const __half* src = Vh + (size_t)b * SEQ * EMBED;
    #pragma unroll
    for (int i = 0; i < 4; ++i)
        t[ty + 8 * i][tx] = src[(size_t)(n0 + ty + 8 * i) * EMBED + e0 + tx];
    __syncthreads();
    __half* dst = VB + (size_t)b * EMBED * SEQ;
    #pragma unroll
    for (int i = 0; i < 4; ++i)
        dst[(size_t)(e0 + ty + 8 * i) * SEQ + n0 + tx] = t[tx][ty + 8 * i];
}

// ---------------- softmax on fp16 scores -> fp16 probs ------------------------
__global__ void softmax_pa_kernel(const __half* __restrict__ s, __half* __restrict__ PA)
{
    __shared__ float row[SEQ];
    __shared__ float red[8];
    const int tid = threadIdx.x;

    // one uint4 = 8 halves per thread covers the whole 2048-wide row
    const uint4 t = reinterpret_cast<const uint4*>(s + (size_t)blockIdx.x * SEQ)[tid];
    const uint32_t w[4] = { t.x, t.y, t.z, t.w };
    float v[8];
    float lmax = -3.4e38f;
    #pragma unroll
    for (int j = 0; j < 4; ++j) {
        const float2 f = __half22float2(*reinterpret_cast<const __half2*>(&w[j]));
        v[2 * j + 0] = f.x;  v[2 * j + 1] = f.y;
        lmax = fmaxf(lmax, fmaxf(f.x, f.y));
    }
    #pragma unroll
    for (int j = 0; j < 8; ++j) row[tid * 8 + j] = v[j];

    #pragma unroll
    for (int o = 16; o; o >>= 1) lmax = fmaxf(lmax, __shfl_xor_sync(0xffffffffu, lmax, o));
    if ((tid & 31) == 0) red[tid >> 5] = lmax;
    __syncthreads();
    const float rmax = fmaxf(fmaxf(fmaxf(red[0], red[1]), fmaxf(red[2], red[3])),
                             fmaxf(fmaxf(red[4], red[5]), fmaxf(red[6], red[7])));
    __syncthreads();

    float lsum = 0.0f;
    #pragma unroll
    for (int j = 0; j < 8; ++j) {
        v[j] = expf(row[tid * 8 + j] - rmax);
        lsum += v[j];
    }
    #pragma unroll
    for (int o = 16; o; o >>= 1) lsum += __shfl_xor_sync(0xffffffffu, lsum, o);
    if ((tid & 31) == 0) red[tid >> 5] = lsum;
    __syncthreads();
    const float inv = 1.0f / (((red[0] + red[1]) + (red[2] + red[3])) +
                              ((red[4] + red[5]) + (red[6] + red[7])));

    uint32_t o[4];
    #pragma unroll
    for (int j = 0; j < 4; ++j) {
        const __half2 hp(__float2half(v[2 * j + 0] * inv), __float2half(v[2 * j + 1] * inv));
        o[j] = *reinterpret_cast<const uint32_t*>(&hp);
    }
    reinterpret_cast<uint4*>(PA + (size_t)blockIdx.x * SEQ)[tid] =
        make_uint4(o[0], o[1], o[2], o[3]);
}

// -----------------------------------------------------------------------------
extern "C" void kernel_launch(void* const* d_in, const int* in_sizes, int n_in,
                              void* d_out, int out_size)
{
    const float* x = (const float*)d_in[0];
    const float* W = (const float*)d_in[1];
    const float* b = (const float*)d_in[2];
    float* out = (float*)d_out;

    __half *sc, *Vh, *A1, *B1, *QA, *KB, *VB, *PA;
    { void* p; cudaGetSymbolAddress(&p, g_sc); sc = (__half*)p; }
    { void* p; cudaGetSymbolAddress(&p, g_Vh); Vh = (__half*)p; }
    { void* p; cudaGetSymbolAddress(&p, g_A1); A1 = (__half*)p; }
    { void* p; cudaGetSymbolAddress(&p, g_B1); B1 = (__half*)p; }
    { void* p; cudaGetSymbolAddress(&p, g_QA); QA = (__half*)p; }
    { void* p; cudaGetSymbolAddress(&p, g_KB); KB = (__half*)p; }
    { void* p; cudaGetSymbolAddress(&p, g_VB); VB = (__half*)p; }
    { void* p; cudaGetSymbolAddress(&p, g_PA); PA = (__half*)p; }

    cudaFuncSetAttribute(mma_gemm<0>, cudaFuncAttributeMaxDynamicSharedMemorySize, SMEM_B);
    cudaFuncSetAttribute(mma_gemm<1>, cudaFuncAttributeMaxDynamicSharedMemorySize, SMEM_B);
    cudaFuncSetAttribute(mma_gemm<2>, cudaFuncAttributeMaxDynamicSharedMemorySize, SMEM_B);

    const long long MN = (long long)BATCH * SEQ;   // 16384

    // input converts: x -> A1 fp16, W -> B1 fp16 (single launch)
    {
        const long long nA = MN * EMBED / 4;
        const long long nB = (long long)QKVD * EMBED / 4;
        cvt2_kernel<<<(unsigned)((nA + nB + 255) / 256), 256>>>(x, A1, nA, W, B1, nB);
    }

    // GEMM1 (fused): qkv = x @ W^T + b  (Keff=1024) -> QA/KB/Vh fp16
    mma_gemm<1><<<dim3(QKVD / 128, (unsigned)(MN / 128), 1), 256, SMEM_B>>>(
        A1, B1, b, nullptr, QA, KB, Vh,
        EMBED, 0, 0, 0, 0, 1.0f);

    // V transpose -> fp16
    vtrans_kernel<<<dim3(SEQ / 32, EMBED / 32, BATCH), dim3(32, 8)>>>(Vh, VB);

    // GEMM2: scores(fp16) = Q @ K^T / 32   (per batch M=N=2048, Keff=1024)
    mma_gemm<2><<<dim3(SEQ / 128, SEQ / 128, BATCH), 256, SMEM_B>>>(
        QA, KB, nullptr, reinterpret_cast<float*>(sc), nullptr, nullptr, nullptr,
        EMBED, SEQ,
        (long long)SEQ * EMBED, (long long)SEQ * EMBED, (long long)SEQ * SEQ,
        0.03125f);

    // softmax (fp16 in) -> fp16 probs
    softmax_pa_kernel<<<BATCH * SEQ, 256>>>(sc, PA);

    // GEMM3: out = P @ V   (per batch M=2048, N=1024, Keff=2048) -> fp32
    mma_gemm<0><<<dim3(EMBED / 128, SEQ / 128, BATCH), 256, SMEM_B>>>(
        PA, VB, nullptr, out, nullptr, nullptr, nullptr,
        SEQ, EMBED,
        (long long)SEQ * SEQ, (long long)EMBED * SEQ, (long long)SEQ * EMBED,
        1.0f);
}